// round 15
// baseline (speedup 1.0000x reference)
#include <cuda_runtime.h>
#include <cuda_fp16.h>
#include <cstdint>

// ---------------------------------------------------------------------------
// Problem constants
// ---------------------------------------------------------------------------
#define BB   64
#define CIN  64
#define COUT 128
#define HH   1855
#define KK   6
#define GH   4
#define NCTA ((HH + GH - 1) / GH)   // 464

// ---------------------------------------------------------------------------
// Device global scratch
//   g_X: [h][b][c] fp16, 4096 elems (8 KB) per h
//   g_W: [j][o][c] fp16, 8192 elems (16 KB) per j   (j = 0 center, 1..6 nbr)
// ---------------------------------------------------------------------------
__device__ __half g_X[(size_t)HH * 4096];   // ~15.2 MB
__device__ __half g_W[7 * 8192];
__device__ __half g_zero[4096];             // 8 KB zeros

// Padded smem rows: 64 fp16 data + 8 pad = 144 B (conflict-free ldmatrix)
#define RS     144
#define W_TILE (128 * RS)                 // 18432 B
#define X_TILE (64 * RS)                  //  9216 B
#define STAGE  (W_TILE + GH * X_TILE)     // 55296 B
#define DSMEM  (2 * STAGE)                // 110592 B -> 1 CTA/SM, 16 warps

// Epilogue scratch: [b(32)][o(128)][h(4)] floats, padded row = 516 floats
#define EROW   516                        // 128*4 + 4 pad
// 32 * 516 * 4 = 66048 B <= DSMEM ✓

// ---------------------------------------------------------------------------
// PTX helpers (plain sm_80+ PTX)
// ---------------------------------------------------------------------------
__device__ __forceinline__ uint32_t smem_u32(const void* p) {
    uint32_t a;
    asm("{ .reg .u64 t; cvta.to.shared.u64 t, %1; cvt.u32.u64 %0, t; }"
        : "=r"(a) : "l"(p));
    return a;
}

__device__ __forceinline__ void cp16(uint32_t dst, const void* src) {
    asm volatile("cp.async.cg.shared.global [%0], [%1], 16;"
                 :: "r"(dst), "l"(src) : "memory");
}
__device__ __forceinline__ void cp_commit() {
    asm volatile("cp.async.commit_group;" ::: "memory");
}
__device__ __forceinline__ void cp_wait1() {
    asm volatile("cp.async.wait_group 1;" ::: "memory");
}
__device__ __forceinline__ void cp_wait0() {
    asm volatile("cp.async.wait_group 0;" ::: "memory");
}

__device__ __forceinline__ void ldsm4(uint32_t* r, uint32_t addr) {
    asm volatile("ldmatrix.sync.aligned.m8n8.x4.shared.b16 {%0,%1,%2,%3}, [%4];"
                 : "=r"(r[0]), "=r"(r[1]), "=r"(r[2]), "=r"(r[3]) : "r"(addr));
}

__device__ __forceinline__ void mma16816(float* c, const uint32_t* a,
                                         const uint32_t* b) {
    asm volatile(
        "mma.sync.aligned.m16n8k16.row.col.f32.f16.f16.f32 "
        "{%0,%1,%2,%3}, {%4,%5,%6,%7}, {%8,%9}, {%0,%1,%2,%3};"
        : "+f"(c[0]), "+f"(c[1]), "+f"(c[2]), "+f"(c[3])
        : "r"(a[0]), "r"(a[1]), "r"(a[2]), "r"(a[3]), "r"(b[0]), "r"(b[1]));
}

// ---------------------------------------------------------------------------
// Kernel 1: transpose x[b][c][h] -> g_X[h][b][c] fp16.
// grid = (64 b, 58 h-tiles), 256 threads
// ---------------------------------------------------------------------------
__global__ void k_prep(const float* __restrict__ x) {
    __shared__ float s[64][33];
    const int b   = blockIdx.x;
    const int h0  = blockIdx.y * 32;
    const int tid = threadIdx.x;

    for (int e = tid; e < 64 * 32; e += 256) {
        int c = e >> 5, hh = e & 31;
        int h = h0 + hh;
        s[c][hh] = (h < HH) ? x[((size_t)(b * CIN + c)) * HH + h] : 0.f;
    }
    __syncthreads();

    // 256 items: [hh(32)][oct(8)], each a uint4 (8 fp16)
    for (int e = tid; e < 256; e += 256) {
        int hh = e >> 3, oct = e & 7;
        int h = h0 + hh;
        if (h >= HH) continue;
        unsigned int r[4];
        #pragma unroll
        for (int p = 0; p < 4; p++) {
            __half v0 = __float2half_rn(s[oct * 8 + 2 * p + 0][hh]);
            __half v1 = __float2half_rn(s[oct * 8 + 2 * p + 1][hh]);
            r[p] = (unsigned)__half_as_ushort(v0)
                 | ((unsigned)__half_as_ushort(v1) << 16);
        }
        __half* dst = g_X + (size_t)h * 4096 + b * 64 + oct * 8;
        *(uint4*)dst = make_uint4(r[0], r[1], r[2], r[3]);
    }
}

// ---------------------------------------------------------------------------
// Kernel 2: pack weights -> g_W[j][o][c] fp16
// ---------------------------------------------------------------------------
__global__ void k_packW(const float* __restrict__ wc, const float* __restrict__ wn) {
    int i = blockIdx.x * 256 + threadIdx.x;      // 7*128*64 = 57344
    if (i < 7 * COUT * CIN) {
        int j = i >> 13;
        int o = (i >> 6) & 127;
        int c = i & 63;
        float w = (j == 0) ? wc[o * CIN + c] : wn[(o * CIN + c) * KK + (j - 1)];
        g_W[(size_t)j * 8192 + o * 64 + c] = __float2half_rn(w);
    }
}

__global__ void k_zero() {
    int i = blockIdx.x * 1024 + threadIdx.x;
    if (i < 4096) g_zero[i] = __float2half(0.f);
}

// ---------------------------------------------------------------------------
// Kernel 3: HMMA conv, fp16 single-pass.  CTA = 4 hexagons, 512 thr = 16 warps
// Warp map: wh = wid & 3 (hexagon), wb = (wid>>2)&1, wo = wid>>3.
// Per h:  D[o=128, b=64] = sum_j W_j[o, 64c] * X_{n(h,j)}[b, 64c]^T.
// Double-buffered cp.async over the 7 K-chunks; epilogue produces 16B-
// contiguous h-quads per (b,o) via smem transpose (two b-halves).
// ---------------------------------------------------------------------------
__global__ __launch_bounds__(512, 1)
void k_conv(const int* __restrict__ nbr, const float* __restrict__ bias,
            float* __restrict__ out) {
    extern __shared__ char dsm[];
    const uint32_t base = smem_u32(dsm);

    __shared__ int   s_sidx[GH][7];
    __shared__ float s_inv[GH];
    __shared__ float s_bias[COUT];

    const int tid  = threadIdx.x;
    const int lane = tid & 31;
    const int wid  = tid >> 5;
    const int wh = wid & 3;           // hexagon
    const int wb = (wid >> 2) & 1;    // b 32-half
    const int wo = wid >> 3;          // o 64-half
    const int h0 = blockIdx.x * GH;
    const int gcnt = min(GH, HH - h0);

    if (tid < GH * 7) {
        int hh = tid / 7, j = tid % 7;
        int v = -1;
        int h = h0 + hh;
        if (h < HH) v = (j == 0) ? h : nbr[h * KK + (j - 1)];
        s_sidx[hh][j] = v;
    }
    if (tid < COUT) s_bias[tid] = bias[tid];
    __syncthreads();
    if (tid < GH) {
        int cnt = 1;
        #pragma unroll
        for (int j = 1; j < 7; j++) cnt += (s_sidx[tid][j] >= 0);
        s_inv[tid] = 1.0f / (float)cnt;
    }
    __syncthreads();

    // ---- cp.async stage issue: W 1024 + X 2048 chunks of 16 B ----
    auto issue_stage = [&](int j, int s) {
        const uint32_t sb = base + s * STAGE;
        const char* wsrc = (const char*)g_W + (size_t)j * 16384;
        for (int i = tid; i < 1024; i += 512) {
            int row = i >> 3, oct = i & 7;
            cp16(sb + row * RS + oct * 16, wsrc + row * 128 + oct * 16);
        }
        for (int i = tid; i < 2048; i += 512) {
            int h   = i >> 9;
            int row = (i >> 3) & 63;
            int oct = i & 7;
            int hv  = s_sidx[h][j];
            const char* xsrc = (hv >= 0)
                ? (const char*)g_X + (size_t)hv * 8192
                : (const char*)g_zero;
            cp16(sb + W_TILE + h * X_TILE + row * RS + oct * 16,
                 xsrc + row * 128 + oct * 16);
        }
        cp_commit();
    };

    issue_stage(0, 0);
    issue_stage(1, 1);

    // ---- fragment address offsets ----
    const uint32_t aoff = (uint32_t)(wo * 64 + (lane & 15)) * RS + (lane >> 4) * 16;
    const uint32_t boff = (uint32_t)(wb * 32 + (lane & 7) + (lane >> 4) * 8) * RS
                        + ((lane >> 3) & 1) * 16;

    float acc[4][4][4];
    #pragma unroll
    for (int mi = 0; mi < 4; mi++)
        #pragma unroll
        for (int ni = 0; ni < 4; ni++)
            #pragma unroll
            for (int c = 0; c < 4; c++) acc[mi][ni][c] = 0.f;

    for (int j = 0; j < 7; j++) {
        const int s = j & 1;
        if (j == 6) cp_wait0(); else cp_wait1();
        __syncthreads();

        const uint32_t Wb = base + s * STAGE;
        const uint32_t Xb = Wb + W_TILE + wh * X_TILE;

        #pragma unroll
        for (int ks = 0; ks < 4; ks++) {
            const uint32_t kb = ks * 32;
            uint32_t ah[4][4], bh[2][4];
            #pragma unroll
            for (int mi = 0; mi < 4; mi++)
                ldsm4(ah[mi], Wb + aoff + mi * 16 * RS + kb);
            ldsm4(bh[0], Xb + boff + kb);
            ldsm4(bh[1], Xb + boff + 16 * RS + kb);
            #pragma unroll
            for (int mi = 0; mi < 4; mi++)
                #pragma unroll
                for (int ni = 0; ni < 4; ni++)
                    mma16816(acc[mi][ni], ah[mi], &bh[ni >> 1][(ni & 1) * 2]);
        }
        __syncthreads();                  // all reads of buffer s done
        if (j + 2 <= 6) issue_stage(j + 2, s);
    }

    // ---- epilogue: two b-halves; smem layout [brel(32)][o(128)][h(4)] ----
    const float inv = s_inv[wh];
    float* S = (float*)dsm;
    for (int half = 0; half < 2; half++) {
        __syncthreads();
        if (wb == half) {
            #pragma unroll
            for (int mi = 0; mi < 4; mi++)
                #pragma unroll
                for (int ni = 0; ni < 4; ni++)
                    #pragma unroll
                    for (int c = 0; c < 4; c++) {
                        int o    = wo * 64 + mi * 16 + (lane >> 2) + ((c & 2) ? 8 : 0);
                        int brel = ni * 8 + (lane & 3) * 2 + (c & 1);
                        S[brel * EROW + o * 4 + wh] =
                            acc[mi][ni][c] * inv + s_bias[o];
                    }
        }
        __syncthreads();
        // 4096 (b,o) cells, 16 B contiguous h-quad each
        for (int i = tid; i < 32 * COUT; i += 512) {
            int brel = i >> 7, o = i & 127;
            int b = half * 32 + brel;
            float4 v = *(const float4*)&S[brel * EROW + o * 4];
            size_t addr = ((size_t)(b * COUT + o)) * HH + h0;
            out[addr] = v.x;
            if (1 < gcnt) out[addr + 1] = v.y;
            if (2 < gcnt) out[addr + 2] = v.z;
            if (3 < gcnt) out[addr + 3] = v.w;
        }
    }
}

// ---------------------------------------------------------------------------
extern "C" void kernel_launch(void* const* d_in, const int* in_sizes, int n_in,
                              void* d_out, int out_size) {
    const float* x    = (const float*)d_in[0];
    const int*   nbr  = (const int*)  d_in[1];
    const float* wc   = (const float*)d_in[2];
    const float* wn   = (const float*)d_in[3];
    const float* bias = (const float*)d_in[4];
    float*       out  = (float*)d_out;

    cudaFuncSetAttribute(k_conv, cudaFuncAttributeMaxDynamicSharedMemorySize,
                         DSMEM);

    k_prep <<<dim3(64, (HH + 31) / 32), 256>>>(x);
    k_packW<<<(7 * COUT * CIN + 255) / 256, 256>>>(wc, wn);
    k_zero <<<4, 1024>>>();
    k_conv <<<NCTA, 512, DSMEM>>>(nbr, bias, out);
}